// round 9
// baseline (speedup 1.0000x reference)
#include <cuda_runtime.h>
#include <math.h>

// ---------------------------------------------------------------------------
// ConnectedFilterLayerWithImplicitJacobian — fused persistent prelude
//   Phase 1: filtered = residues*sigmoid(attrs@w+b), 4 nodes/thread vectorized
//       pack[tpre[i]] = {+f,i}; pack[tpost[i]] = {-f,-1}   (permutation)
//   grid barrier (123 blocks, all resident: spin-safe)
//   Phase 2: decoupled-lookback scan of pack.x; at tpre slots scatter the
//       final prefix straight into y_node[node].
//   k_gather: out[p] = y_node[node_of_pixel[p]]  (L1tex wavefront floor ~41us)
// ---------------------------------------------------------------------------

#define TMAX     (1 << 20)          // 2N = 1,000,000 <= 1,048,576
#define NMAX     (1 << 19)          // N = 500,000 <= 524,288
#define STILE    8192
#define STHREADS 1024
#define SIPT     (STILE / STHREADS) // 8 packed elems per thread

__device__ float2 g_pack[TMAX];     // .x = delta value, .y = node id bits
__device__ float  g_ynode[NMAX];
__device__ unsigned long long g_desc[256];   // lookback descriptors
__device__ unsigned g_sync1 = 0;             // barrier arrive counter
__device__ unsigned g_sync2 = 0;             // epilogue counter (resets sync)

#define FLAG_AGG 1u
#define FLAG_PRE 2u

__device__ __forceinline__ unsigned long long pack_desc(float v, unsigned f) {
    return ((unsigned long long)f << 32) | (unsigned long long)__float_as_uint(v);
}

// ---------------- fused kernel: filtered + grid sync + scan ----------------
__global__ __launch_bounds__(STHREADS) void k_fused(
    const float* __restrict__ weight,
    const float* __restrict__ bias,
    const float* __restrict__ residues,
    const float* __restrict__ attrs,
    const int*   __restrict__ tpre,
    const int*   __restrict__ tpost,
    int n, int T)
{
    int b  = blockIdx.x;
    int nb = gridDim.x;
    int t  = threadIdx.x;
    int lane = t & 31;
    int w = t >> 5;

    if (t == 0) g_desc[b] = 0ull;

    int gtid   = b * STHREADS + t;
    int stride = nb * STHREADS;

    // ------------- phase 1: filtered + packed scatter, 4 nodes/thread ------
    {
        float4 w0 = *reinterpret_cast<const float4*>(weight);
        float4 w1 = *(reinterpret_cast<const float4*>(weight) + 1);
        float  b0 = bias[0];

        int nq = n >> 2;   // groups of 4 nodes
        for (int q = gtid; q < nq; q += stride) {
            int i = q * 4;
            int4   pr = *reinterpret_cast<const int4*>(tpre + i);
            int4   po = *reinterpret_cast<const int4*>(tpost + i);
            float4 rr = *reinterpret_cast<const float4*>(residues + i);
            const float4* a = reinterpret_cast<const float4*>(attrs + (size_t)i * 8);
            float4 a0 = a[0], a1 = a[1], a2 = a[2], a3 = a[3];
            float4 a4 = a[4], a5 = a[5], a6 = a[6], a7 = a[7];

            float l0 = a0.x*w0.x + a0.y*w0.y + a0.z*w0.z + a0.w*w0.w
                     + a1.x*w1.x + a1.y*w1.y + a1.z*w1.z + a1.w*w1.w + b0;
            float l1 = a2.x*w0.x + a2.y*w0.y + a2.z*w0.z + a2.w*w0.w
                     + a3.x*w1.x + a3.y*w1.y + a3.z*w1.z + a3.w*w1.w + b0;
            float l2 = a4.x*w0.x + a4.y*w0.y + a4.z*w0.z + a4.w*w0.w
                     + a5.x*w1.x + a5.y*w1.y + a5.z*w1.z + a5.w*w1.w + b0;
            float l3 = a6.x*w0.x + a6.y*w0.y + a6.z*w0.z + a6.w*w0.w
                     + a7.x*w1.x + a7.y*w1.y + a7.z*w1.z + a7.w*w1.w + b0;

            float f0 = rr.x * (1.0f / (1.0f + expf(-l0)));
            float f1 = rr.y * (1.0f / (1.0f + expf(-l1)));
            float f2 = rr.z * (1.0f / (1.0f + expf(-l2)));
            float f3 = rr.w * (1.0f / (1.0f + expf(-l3)));

            __stcg(&g_pack[pr.x], make_float2( f0, __int_as_float(i)));
            __stcg(&g_pack[pr.y], make_float2( f1, __int_as_float(i + 1)));
            __stcg(&g_pack[pr.z], make_float2( f2, __int_as_float(i + 2)));
            __stcg(&g_pack[pr.w], make_float2( f3, __int_as_float(i + 3)));
            __stcg(&g_pack[po.x], make_float2(-f0, __int_as_float(-1)));
            __stcg(&g_pack[po.y], make_float2(-f1, __int_as_float(-1)));
            __stcg(&g_pack[po.z], make_float2(-f2, __int_as_float(-1)));
            __stcg(&g_pack[po.w], make_float2(-f3, __int_as_float(-1)));
        }
        // Tail (n not divisible by 4)
        for (int i = nq * 4 + gtid; i < n; i += stride) {
            const float4* a = reinterpret_cast<const float4*>(attrs + (size_t)i * 8);
            float4 a0 = a[0], a1 = a[1];
            float logit = a0.x*w0.x + a0.y*w0.y + a0.z*w0.z + a0.w*w0.w
                        + a1.x*w1.x + a1.y*w1.y + a1.z*w1.z + a1.w*w1.w + b0;
            float f = residues[i] * (1.0f / (1.0f + expf(-logit)));
            __stcg(&g_pack[tpre[i]],  make_float2( f, __int_as_float(i)));
            __stcg(&g_pack[tpost[i]], make_float2(-f, __int_as_float(-1)));
        }
    }

    // ---------------- grid barrier ------------------------------------------
    __syncthreads();
    if (t == 0) {
        __threadfence();
        atomicAdd(&g_sync1, 1u);
        while (*(volatile unsigned*)&g_sync1 < (unsigned)nb)
            __nanosleep(32);
        __threadfence();
    }
    __syncthreads();

    // ---------------- phase 2: lookback scan on tile b ----------------------
    __shared__ float s_excl;
    __shared__ float s_warp[STHREADS / 32];

    int base = b * STILE;
    bool full = (base + STILE <= T);

    float e[SIPT];
    int   nd[SIPT];
    if (full) {
        const float4* src = reinterpret_cast<const float4*>(g_pack + base + t * SIPT);
#pragma unroll
        for (int q = 0; q < SIPT / 2; q++) {
            float4 v = __ldcs(src + q);
            e[q*2+0] = v.x;  nd[q*2+0] = __float_as_int(v.y);
            e[q*2+1] = v.z;  nd[q*2+1] = __float_as_int(v.w);
        }
    } else {
#pragma unroll
        for (int j = 0; j < SIPT; j++) {
            int g = base + t * SIPT + j;
            if (g < T) {
                float2 v = __ldcg(&g_pack[g]);
                e[j] = v.x;
                nd[j] = __float_as_int(v.y);
            } else {
                e[j] = 0.0f;
                nd[j] = -1;
            }
        }
    }

    float run = 0.0f;
#pragma unroll
    for (int j = 0; j < SIPT; j++) { run += e[j]; e[j] = run; }

    float incl = run;
#pragma unroll
    for (int o = 1; o < 32; o <<= 1) {
        float nbr = __shfl_up_sync(0xffffffffu, incl, o);
        if (lane >= o) incl += nbr;
    }
    if (lane == 31) s_warp[w] = incl;
    __syncthreads();
    if (t == 0) {
        float acc = 0.0f;
#pragma unroll
        for (int k = 0; k < STHREADS / 32; k++) { acc += s_warp[k]; s_warp[k] = acc; }
    }
    __syncthreads();
    float thr_excl = incl - run + (w > 0 ? s_warp[w - 1] : 0.0f);
    float block_total = s_warp[STHREADS / 32 - 1];

    if (t == 0) {
        unsigned long long d = (b == 0) ? pack_desc(block_total, FLAG_PRE)
                                        : pack_desc(block_total, FLAG_AGG);
        atomicExch(&g_desc[b], d);
        if (b == 0) s_excl = 0.0f;
    }

    if (b > 0 && w == 0) {
        float running = 0.0f;
        int tile_idx = b - 1;
        while (true) {
            int idx = tile_idx - lane;
            unsigned f;
            float val;
            if (idx < 0) { f = FLAG_PRE; val = 0.0f; }
            else {
                unsigned long long d;
                do {
                    d = *((volatile unsigned long long*)&g_desc[idx]);
                    f = (unsigned)(d >> 32);
                } while (f == 0u);
                val = __uint_as_float((unsigned)(d & 0xffffffffull));
            }
            unsigned pmask = __ballot_sync(0xffffffffu, f == FLAG_PRE);
            if (pmask) {
                int fp = __ffs(pmask) - 1;
                float c = (lane <= fp) ? val : 0.0f;
#pragma unroll
                for (int o = 16; o > 0; o >>= 1) c += __shfl_xor_sync(0xffffffffu, c, o);
                running += c;
                break;
            } else {
                float c = val;
#pragma unroll
                for (int o = 16; o > 0; o >>= 1) c += __shfl_xor_sync(0xffffffffu, c, o);
                running += c;
                tile_idx -= 32;
            }
        }
        if (lane == 0) {
            s_excl = running;
            atomicExch(&g_desc[b], pack_desc(running + block_total, FLAG_PRE));
        }
    }
    __syncthreads();
    float add = s_excl + thr_excl;

#pragma unroll
    for (int j = 0; j < SIPT; j++) {
        int node = nd[j];
        if (node >= 0) __stcg(&g_ynode[node], e[j] + add);
    }

    // ---------------- epilogue: last block resets barrier state -------------
    __syncthreads();
    if (t == 0) {
        unsigned o = atomicAdd(&g_sync2, 1u);
        if (o == (unsigned)(nb - 1)) {
            g_sync1 = 0u;
            g_sync2 = 0u;
        }
    }
}

// --------------- per-pixel gather (R2 exact config: best measured) ----------
__global__ __launch_bounds__(256) void k_gather(const int* __restrict__ nop,
                                                float* __restrict__ out,
                                                int P)
{
    int i = (blockIdx.x * blockDim.x + threadIdx.x) * 8;
    if (i + 7 < P) {
        int4 n0 = *reinterpret_cast<const int4*>(nop + i);
        int4 n1 = *reinterpret_cast<const int4*>(nop + i + 4);
        float4 r0, r1;
        r0.x = g_ynode[n0.x];
        r0.y = g_ynode[n0.y];
        r0.z = g_ynode[n0.z];
        r0.w = g_ynode[n0.w];
        r1.x = g_ynode[n1.x];
        r1.y = g_ynode[n1.y];
        r1.z = g_ynode[n1.z];
        r1.w = g_ynode[n1.w];
        *reinterpret_cast<float4*>(out + i)     = r0;
        *reinterpret_cast<float4*>(out + i + 4) = r1;
    } else {
        for (int j = i; j < P; j++) out[j] = g_ynode[nop[j]];
    }
}

// ---------------------------------------------------------------------------
extern "C" void kernel_launch(void* const* d_in, const int* in_sizes, int n_in,
                              void* d_out, int out_size)
{
    const float* weight   = (const float*)d_in[0];
    const float* bias     = (const float*)d_in[1];
    const float* residues = (const float*)d_in[2];
    const float* attrs    = (const float*)d_in[3];
    const int*   tpre     = (const int*)d_in[4];
    const int*   tpost    = (const int*)d_in[5];
    const int*   nop      = (const int*)d_in[6];

    int N = in_sizes[2];
    int P = in_sizes[6];
    int T = 2 * N;
    int nb = (T + STILE - 1) / STILE;     // 123 blocks, all resident

    k_fused<<<nb, STHREADS>>>(weight, bias, residues, attrs, tpre, tpost, N, T);

    int gt = (P + 7) / 8;
    k_gather<<<(gt + 255) / 256, 256>>>(nop, (float*)d_out, P);
}

// round 10
// speedup vs baseline: 1.0348x; 1.0348x over previous
#include <cuda_runtime.h>
#include <math.h>

// ---------------------------------------------------------------------------
// ConnectedFilterLayerWithImplicitJacobian
//   filtered = residues * sigmoid(attrs2d @ w + b)
//   pack[tpre[i]]  = {+f, i};  pack[tpost[i]] = {-f, -1}   (permutation)
//   scan pack.x with decoupled lookback; at tpre slots scatter final prefix
//   straight into y_node[node].
//   out[p] = y_node[node_of_pixel[p]]  — software-pipelined strided gather.
// ---------------------------------------------------------------------------

#define TMAX     (1 << 20)          // 2N = 1,000,000 <= 1,048,576
#define NMAX     (1 << 19)          // N = 500,000 <= 524,288
#define STILE    8192
#define STHREADS 512
#define SIPT     (STILE / STHREADS) // 16 packed elems per thread

__device__ float2 g_pack[TMAX];     // .x = delta value, .y = node id bits
__device__ float  g_ynode[NMAX];
// [0] = ticket counter, [1..] = lookback descriptors (flag<<32 | float bits)
__device__ unsigned long long g_scan_state[256];

#define FLAG_AGG 1u
#define FLAG_PRE 2u

__device__ __forceinline__ unsigned long long pack_desc(float v, unsigned f) {
    return ((unsigned long long)f << 32) | (unsigned long long)__float_as_uint(v);
}

// --------------- kernel 1: filtered + packed scatter (+ state reset) -------
__global__ void k_filtered(const float* __restrict__ weight,
                           const float* __restrict__ bias,
                           const float* __restrict__ residues,
                           const float* __restrict__ attrs,
                           const int*   __restrict__ tpre,
                           const int*   __restrict__ tpost,
                           int n, int nstate)
{
    if (blockIdx.x == 0 && threadIdx.x < nstate)
        g_scan_state[threadIdx.x] = 0ull;

    int i = blockIdx.x * blockDim.x + threadIdx.x;
    if (i >= n) return;

    const float4* a = reinterpret_cast<const float4*>(attrs + (size_t)i * 8);
    float4 a0 = a[0];
    float4 a1 = a[1];
    float4 w0 = *reinterpret_cast<const float4*>(weight);
    float4 w1 = *(reinterpret_cast<const float4*>(weight) + 1);

    float logit = a0.x * w0.x + a0.y * w0.y + a0.z * w0.z + a0.w * w0.w
                + a1.x * w1.x + a1.y * w1.y + a1.z * w1.z + a1.w * w1.w
                + bias[0];
    float s = 1.0f / (1.0f + __expf(-logit));
    float f = residues[i] * s;

    __stcg(&g_pack[tpre[i]],  make_float2( f, __int_as_float(i)));
    __stcg(&g_pack[tpost[i]], make_float2(-f, __int_as_float(-1)));
}

// ------- kernel 2: single-pass lookback scan + direct ynode scatter --------
__global__ __launch_bounds__(STHREADS) void k_scan(int T)
{
    __shared__ unsigned s_bid;
    __shared__ float    s_excl;
    __shared__ float    s_warp[STHREADS / 32];

    int t = threadIdx.x;
    int lane = t & 31;
    int w = t >> 5;

    if (t == 0) s_bid = atomicAdd((unsigned int*)&g_scan_state[0], 1u);
    __syncthreads();
    int b = (int)s_bid;
    unsigned long long* desc = g_scan_state + 1;

    int base = b * STILE;
    bool full = (base + STILE <= T);

    float e[SIPT];
    int   nd[SIPT];
    if (full) {
        const float4* src = reinterpret_cast<const float4*>(g_pack + base + t * SIPT);
#pragma unroll
        for (int q = 0; q < SIPT / 2; q++) {
            float4 v = __ldcs(src + q);
            e[q*2+0] = v.x;  nd[q*2+0] = __float_as_int(v.y);
            e[q*2+1] = v.z;  nd[q*2+1] = __float_as_int(v.w);
        }
    } else {
#pragma unroll
        for (int j = 0; j < SIPT; j++) {
            int g = base + t * SIPT + j;
            if (g < T) {
                float2 v = g_pack[g];
                e[j] = v.x;
                nd[j] = __float_as_int(v.y);
            } else {
                e[j] = 0.0f;
                nd[j] = -1;
            }
        }
    }

    float run = 0.0f;
#pragma unroll
    for (int j = 0; j < SIPT; j++) { run += e[j]; e[j] = run; }

    float incl = run;
#pragma unroll
    for (int o = 1; o < 32; o <<= 1) {
        float nbr = __shfl_up_sync(0xffffffffu, incl, o);
        if (lane >= o) incl += nbr;
    }
    if (lane == 31) s_warp[w] = incl;
    __syncthreads();
    if (t == 0) {
        float acc = 0.0f;
#pragma unroll
        for (int k = 0; k < STHREADS / 32; k++) { acc += s_warp[k]; s_warp[k] = acc; }
    }
    __syncthreads();
    float thr_excl = incl - run + (w > 0 ? s_warp[w - 1] : 0.0f);
    float block_total = s_warp[STHREADS / 32 - 1];

    if (t == 0) {
        unsigned long long d = (b == 0) ? pack_desc(block_total, FLAG_PRE)
                                        : pack_desc(block_total, FLAG_AGG);
        atomicExch(&desc[b], d);
        if (b == 0) s_excl = 0.0f;
    }

    if (b > 0 && w == 0) {
        float running = 0.0f;
        int tile_idx = b - 1;
        while (true) {
            int idx = tile_idx - lane;
            unsigned f;
            float val;
            if (idx < 0) { f = FLAG_PRE; val = 0.0f; }
            else {
                unsigned long long d;
                do {
                    d = *((volatile unsigned long long*)&desc[idx]);
                    f = (unsigned)(d >> 32);
                } while (f == 0u);
                val = __uint_as_float((unsigned)(d & 0xffffffffull));
            }
            unsigned pmask = __ballot_sync(0xffffffffu, f == FLAG_PRE);
            if (pmask) {
                int fp = __ffs(pmask) - 1;
                float c = (lane <= fp) ? val : 0.0f;
#pragma unroll
                for (int o = 16; o > 0; o >>= 1) c += __shfl_xor_sync(0xffffffffu, c, o);
                running += c;
                break;
            } else {
                float c = val;
#pragma unroll
                for (int o = 16; o > 0; o >>= 1) c += __shfl_xor_sync(0xffffffffu, c, o);
                running += c;
                tile_idx -= 32;
            }
        }
        if (lane == 0) {
            s_excl = running;
            atomicExch(&desc[b], pack_desc(running + block_total, FLAG_PRE));
        }
    }
    __syncthreads();
    float add = s_excl + thr_excl;

#pragma unroll
    for (int j = 0; j < SIPT; j++) {
        int node = nd[j];
        if (node >= 0) __stcg(&g_ynode[node], e[j] + add);
    }
}

// ------------- kernel 3: pipelined strided per-pixel gather -----------------
// Each thread processes several 8-pixel chunks with a register double-buffer
// on the index loads, so the 577-cycle nop latency overlaps gather issue.
__global__ __launch_bounds__(256) void k_gather(const int4* __restrict__ nop4,
                                                float* __restrict__ out,
                                                int nchunk, int P)
{
    int tid = blockIdx.x * blockDim.x + threadIdx.x;
    int nthreads = gridDim.x * blockDim.x;

    int k = tid;
    int4 c0, c1;
    if (k < nchunk) {
        c0 = nop4[2 * k];
        c1 = nop4[2 * k + 1];
    }
    while (k < nchunk) {
        int kn = k + nthreads;
        int4 n0 = c0, n1 = c1;
        if (kn < nchunk) {                 // prefetch next chunk's indices
            c0 = nop4[2 * kn];
            c1 = nop4[2 * kn + 1];
        }
        float4 r0, r1;
        r0.x = g_ynode[n0.x];
        r0.y = g_ynode[n0.y];
        r0.z = g_ynode[n0.z];
        r0.w = g_ynode[n0.w];
        r1.x = g_ynode[n1.x];
        r1.y = g_ynode[n1.y];
        r1.z = g_ynode[n1.z];
        r1.w = g_ynode[n1.w];
        float4* dst = reinterpret_cast<float4*>(out + (size_t)k * 8);
        dst[0] = r0;
        dst[1] = r1;
        k = kn;
    }

    // Tail pixels (P not divisible by 8)
    int tail = nchunk * 8;
    for (int j = tail + tid; j < P; j += nthreads)
        out[j] = g_ynode[reinterpret_cast<const int*>(nop4)[j]];
}

// ---------------------------------------------------------------------------
extern "C" void kernel_launch(void* const* d_in, const int* in_sizes, int n_in,
                              void* d_out, int out_size)
{
    const float* weight   = (const float*)d_in[0];
    const float* bias     = (const float*)d_in[1];
    const float* residues = (const float*)d_in[2];
    const float* attrs    = (const float*)d_in[3];
    const int*   tpre     = (const int*)d_in[4];
    const int*   tpost    = (const int*)d_in[5];
    const int*   nop      = (const int*)d_in[6];

    int N = in_sizes[2];
    int P = in_sizes[6];
    int T = 2 * N;
    int nb = (T + STILE - 1) / STILE;     // 123 blocks: single wave

    k_filtered<<<(N + 255) / 256, 256>>>(weight, bias, residues, attrs,
                                         tpre, tpost, N, nb + 1);
    k_scan<<<nb, STHREADS>>>(T);

    int nchunk = P / 8;                   // 8 pixels per chunk
    // ~262k threads: one resident wave, ~4 pipelined chunks per thread.
    int gblocks = 1024;
    k_gather<<<gblocks, 256>>>((const int4*)nop, (float*)d_out, nchunk, P);
}

// round 11
// speedup vs baseline: 1.0360x; 1.0011x over previous
#include <cuda_runtime.h>
#include <math.h>

// ---------------------------------------------------------------------------
// ConnectedFilterLayerWithImplicitJacobian
//   filtered = residues * sigmoid(attrs2d @ w + b)
//   pack[tpre[i]]  = {+f, i};  pack[tpost[i]] = {-f, -1}   (permutation)
//   [leaves: tpost==tpre+1 -> single float4 store when 16B-aligned]
//   scan pack.x with decoupled lookback; at tpre slots scatter final prefix
//   straight into y_node[node].
//   out[p] = y_node[node_of_pixel[p]]   (gather at L1tex wavefront floor)
// ---------------------------------------------------------------------------

#define TMAX     (1 << 20)          // 2N = 1,000,000 <= 1,048,576
#define NMAX     (1 << 19)          // N = 500,000 <= 524,288
#define STILE    8192
#define STHREADS 512
#define SIPT     (STILE / STHREADS) // 16 packed elems per thread

__device__ float2 g_pack[TMAX];     // .x = delta value, .y = node id bits
__device__ float  g_ynode[NMAX];
// [0] = ticket counter, [1..] = lookback descriptors (flag<<32 | float bits)
__device__ unsigned long long g_scan_state[256];

#define FLAG_AGG 1u
#define FLAG_PRE 2u

__device__ __forceinline__ unsigned long long pack_desc(float v, unsigned f) {
    return ((unsigned long long)f << 32) | (unsigned long long)__float_as_uint(v);
}

// --------------- kernel 1: filtered + packed scatter (+ state reset) -------
__global__ void k_filtered(const float* __restrict__ weight,
                           const float* __restrict__ bias,
                           const float* __restrict__ residues,
                           const float* __restrict__ attrs,
                           const int*   __restrict__ tpre,
                           const int*   __restrict__ tpost,
                           int n, int nstate)
{
    if (blockIdx.x == 0 && threadIdx.x < nstate)
        g_scan_state[threadIdx.x] = 0ull;

    int i = blockIdx.x * blockDim.x + threadIdx.x;
    if (i >= n) return;

    int pr = tpre[i];
    int po = tpost[i];

    const float4* a = reinterpret_cast<const float4*>(attrs + (size_t)i * 8);
    float4 a0 = a[0];
    float4 a1 = a[1];
    float4 w0 = *reinterpret_cast<const float4*>(weight);
    float4 w1 = *(reinterpret_cast<const float4*>(weight) + 1);

    float logit = a0.x * w0.x + a0.y * w0.y + a0.z * w0.z + a0.w * w0.w
                + a1.x * w1.x + a1.y * w1.y + a1.z * w1.z + a1.w * w1.w
                + bias[0];
    float s = 1.0f / (1.0f + __expf(-logit));
    float f = residues[i] * s;

    // Leaf with aligned tpre: the two 8B entries are one aligned 16B slot.
    if (po == pr + 1 && (pr & 1) == 0) {
        float4 v;
        v.x = f;  v.y = __int_as_float(i);
        v.z = -f; v.w = __int_as_float(-1);
        __stcg(reinterpret_cast<float4*>(&g_pack[pr]), v);
    } else {
        __stcg(&g_pack[pr], make_float2( f, __int_as_float(i)));
        __stcg(&g_pack[po], make_float2(-f, __int_as_float(-1)));
    }
}

// ------- kernel 2: single-pass lookback scan + direct ynode scatter --------
__global__ __launch_bounds__(STHREADS) void k_scan(int T)
{
    __shared__ unsigned s_bid;
    __shared__ float    s_excl;
    __shared__ float    s_warp[STHREADS / 32];

    int t = threadIdx.x;
    int lane = t & 31;
    int w = t >> 5;

    if (t == 0) s_bid = atomicAdd((unsigned int*)&g_scan_state[0], 1u);
    __syncthreads();
    int b = (int)s_bid;
    unsigned long long* desc = g_scan_state + 1;

    int base = b * STILE;
    bool full = (base + STILE <= T);

    float e[SIPT];
    int   nd[SIPT];
    if (full) {
        const float4* src = reinterpret_cast<const float4*>(g_pack + base + t * SIPT);
#pragma unroll
        for (int q = 0; q < SIPT / 2; q++) {
            float4 v = __ldcs(src + q);
            e[q*2+0] = v.x;  nd[q*2+0] = __float_as_int(v.y);
            e[q*2+1] = v.z;  nd[q*2+1] = __float_as_int(v.w);
        }
    } else {
#pragma unroll
        for (int j = 0; j < SIPT; j++) {
            int g = base + t * SIPT + j;
            if (g < T) {
                float2 v = g_pack[g];
                e[j] = v.x;
                nd[j] = __float_as_int(v.y);
            } else {
                e[j] = 0.0f;
                nd[j] = -1;
            }
        }
    }

    float run = 0.0f;
#pragma unroll
    for (int j = 0; j < SIPT; j++) { run += e[j]; e[j] = run; }

    float incl = run;
#pragma unroll
    for (int o = 1; o < 32; o <<= 1) {
        float nbr = __shfl_up_sync(0xffffffffu, incl, o);
        if (lane >= o) incl += nbr;
    }
    if (lane == 31) s_warp[w] = incl;
    __syncthreads();
    if (t == 0) {
        float acc = 0.0f;
#pragma unroll
        for (int k = 0; k < STHREADS / 32; k++) { acc += s_warp[k]; s_warp[k] = acc; }
    }
    __syncthreads();
    float thr_excl = incl - run + (w > 0 ? s_warp[w - 1] : 0.0f);
    float block_total = s_warp[STHREADS / 32 - 1];

    if (t == 0) {
        unsigned long long d = (b == 0) ? pack_desc(block_total, FLAG_PRE)
                                        : pack_desc(block_total, FLAG_AGG);
        atomicExch(&desc[b], d);
        if (b == 0) s_excl = 0.0f;
    }

    if (b > 0 && w == 0) {
        float running = 0.0f;
        int tile_idx = b - 1;
        while (true) {
            int idx = tile_idx - lane;
            unsigned f;
            float val;
            if (idx < 0) { f = FLAG_PRE; val = 0.0f; }
            else {
                unsigned long long d;
                do {
                    d = *((volatile unsigned long long*)&desc[idx]);
                    f = (unsigned)(d >> 32);
                } while (f == 0u);
                val = __uint_as_float((unsigned)(d & 0xffffffffull));
            }
            unsigned pmask = __ballot_sync(0xffffffffu, f == FLAG_PRE);
            if (pmask) {
                int fp = __ffs(pmask) - 1;
                float c = (lane <= fp) ? val : 0.0f;
#pragma unroll
                for (int o = 16; o > 0; o >>= 1) c += __shfl_xor_sync(0xffffffffu, c, o);
                running += c;
                break;
            } else {
                float c = val;
#pragma unroll
                for (int o = 16; o > 0; o >>= 1) c += __shfl_xor_sync(0xffffffffu, c, o);
                running += c;
                tile_idx -= 32;
            }
        }
        if (lane == 0) {
            s_excl = running;
            atomicExch(&desc[b], pack_desc(running + block_total, FLAG_PRE));
        }
    }
    __syncthreads();
    float add = s_excl + thr_excl;

#pragma unroll
    for (int j = 0; j < SIPT; j++) {
        int node = nd[j];
        if (node >= 0) __stcg(&g_ynode[node], e[j] + add);
    }
}

// --------------- per-pixel gather (R2/R5 exact config: best measured) -------
__global__ __launch_bounds__(512) void k_gather(const int* __restrict__ nop,
                                                float* __restrict__ out,
                                                int P)
{
    int i = (blockIdx.x * blockDim.x + threadIdx.x) * 8;
    if (i + 7 < P) {
        int4 n0 = *reinterpret_cast<const int4*>(nop + i);
        int4 n1 = *reinterpret_cast<const int4*>(nop + i + 4);
        float4 r0, r1;
        r0.x = __ldg(g_ynode + n0.x);
        r0.y = __ldg(g_ynode + n0.y);
        r0.z = __ldg(g_ynode + n0.z);
        r0.w = __ldg(g_ynode + n0.w);
        r1.x = __ldg(g_ynode + n1.x);
        r1.y = __ldg(g_ynode + n1.y);
        r1.z = __ldg(g_ynode + n1.z);
        r1.w = __ldg(g_ynode + n1.w);
        *reinterpret_cast<float4*>(out + i)     = r0;
        *reinterpret_cast<float4*>(out + i + 4) = r1;
    } else {
        for (int j = i; j < P; j++) out[j] = g_ynode[nop[j]];
    }
}

// ---------------------------------------------------------------------------
extern "C" void kernel_launch(void* const* d_in, const int* in_sizes, int n_in,
                              void* d_out, int out_size)
{
    const float* weight   = (const float*)d_in[0];
    const float* bias     = (const float*)d_in[1];
    const float* residues = (const float*)d_in[2];
    const float* attrs    = (const float*)d_in[3];
    const int*   tpre     = (const int*)d_in[4];
    const int*   tpost    = (const int*)d_in[5];
    const int*   nop      = (const int*)d_in[6];

    int N = in_sizes[2];
    int P = in_sizes[6];
    int T = 2 * N;
    int nb = (T + STILE - 1) / STILE;     // 123 blocks: single wave

    k_filtered<<<(N + 255) / 256, 256>>>(weight, bias, residues, attrs,
                                         tpre, tpost, N, nb + 1);
    k_scan<<<nb, STHREADS>>>(T);

    int gt = (P + 7) / 8;
    k_gather<<<(gt + 511) / 512, 512>>>(nop, (float*)d_out, P);
}